// round 1
// baseline (speedup 1.0000x reference)
#include <cuda_runtime.h>
#include <math.h>

#define TPB 512
#define NWARP (TPB / 32)
#define BUFCAP 4096
#define MAXB 4096

__device__ float g_rowloss[MAXB];

__device__ __forceinline__ float warpRedF(float v) {
#pragma unroll
    for (int o = 16; o > 0; o >>= 1) v += __shfl_down_sync(0xffffffffu, v, o);
    return v;
}
__device__ __forceinline__ int warpRedI(int v) {
#pragma unroll
    for (int o = 16; o > 0; o >>= 1) v += __shfl_down_sync(0xffffffffu, v, o);
    return v;
}

__global__ __launch_bounds__(TPB) void topk_bce_kernel(
    const float* __restrict__ scores,
    const float* __restrict__ label,
    const int* __restrict__ seqlen,
    int T)
{
    __shared__ float s_buf[BUFCAP];
    __shared__ int   s_hist[256];
    __shared__ float s_rf[NWARP];
    __shared__ int   s_ri[NWARP];
    __shared__ int   s_ri2[NWARP];
    __shared__ int   s_widx;
    __shared__ float s_Lb, s_Ub;
    __shared__ int   s_status;   // 0 = continue, 1 = select in buffer, 2 = tie (exact thr known)
    __shared__ int   s_m;
    __shared__ int   s_cntU;
    __shared__ float s_sumU;
    __shared__ unsigned s_prefix;
    __shared__ int   s_kk;
    __shared__ float s_thr;

    const int row  = blockIdx.x;
    const int tid  = threadIdx.x;
    const int lane = tid & 31;
    const int wid  = tid >> 5;

    const int n = seqlen[row];
    const int k = (n >> 4) + 1;            // seqlen//16 + 1, always 1..n
    const float*  rp  = scores + (size_t)row * (size_t)T;
    const float4* rp4 = (const float4*)rp;

    // thread-0-only bracket state: kth largest value v satisfies v in (gL, gU]
    float gL = 0.0f, gU = 1.0f;
    bool  tiemode = false;

    if (tid == 0) {
        float L, U;
        if (n <= BUFCAP) {                 // small row: window = everything
            L = 0.0f; U = 1.0f;
        } else {                           // statistical window around quantile 1 - k/n
            float fn = (float)n, fk = (float)k;
            float mean = 1.0f - fk / fn;
            float sig  = sqrtf(fk) / fn;   // >= true Beta std -> conservative
            L = fmaxf(0.0f, mean - 10.0f * sig);
            U = fminf(1.0f, mean + 10.0f * sig);
        }
        s_Lb = L; s_Ub = U;
        s_status = 0;
        s_m = 0; s_thr = 0.5f; s_cntU = 0; s_sumU = 0.0f;   // safe defaults
    }

    const int nv  = n >> 2;
    const int nvr = ((nv + TPB - 1) / TPB) * TPB;   // rounded so all warps iterate uniformly

    for (int iter = 0; iter < 64; ++iter) {
        __syncthreads();
        const float L = s_Lb, U = s_Ub;
        if (tid == 0) s_widx = 0;
        __syncthreads();

        int   cU = 0, cL = 0;
        float sU = 0.0f;

        // streaming pass: count(>L), count(>U), sum(>U), compact (L,U] into s_buf
        for (int i = tid; i < nvr; i += TPB) {
            bool a = i < nv;
            float4 v4 = a ? rp4[i] : make_float4(-1.f, -1.f, -1.f, -1.f);
            float xs[4] = {v4.x, v4.y, v4.z, v4.w};
#pragma unroll
            for (int c = 0; c < 4; ++c) {
                float x = xs[c];
                bool gtU = x > U;
                bool gtL = x > L;
                cL += gtL;
                if (gtU) { cU++; sU += x; }
                bool inw = gtL && !gtU;
                unsigned msk = __ballot_sync(0xffffffffu, inw);
                if (inw) {
                    int leader = __ffs(msk) - 1;
                    int base;
                    if (lane == leader) base = atomicAdd(&s_widx, __popc(msk));
                    base = __shfl_sync(msk, base, leader);
                    int p = base + __popc(msk & ((1u << lane) - 1u));
                    if (p < BUFCAP) s_buf[p] = x;
                }
            }
        }
        {   // tail (< 4 elements), single predicated step, warp-uniform
            int i = (nv << 2) + tid;
            bool a = i < n;
            float x = a ? rp[i] : -1.0f;
            bool gtU = x > U;
            bool gtL = x > L;
            cL += gtL;
            if (gtU) { cU++; sU += x; }
            bool inw = gtL && !gtU;
            unsigned msk = __ballot_sync(0xffffffffu, inw);
            if (inw) {
                int leader = __ffs(msk) - 1;
                int base;
                if (lane == leader) base = atomicAdd(&s_widx, __popc(msk));
                base = __shfl_sync(msk, base, leader);
                int p = base + __popc(msk & ((1u << lane) - 1u));
                if (p < BUFCAP) s_buf[p] = x;
            }
        }

        cU = warpRedI(cU);
        cL = warpRedI(cL);
        sU = warpRedF(sU);
        if (lane == 0) { s_ri[wid] = cU; s_ri2[wid] = cL; s_rf[wid] = sU; }
        __syncthreads();

        if (tid == 0) {
            int CU = 0, CL = 0; float SU = 0.0f;
            for (int j = 0; j < NWARP; ++j) { CU += s_ri[j]; CL += s_ri2[j]; SU += s_rf[j]; }

            if (tiemode) {
                // window collapsed to single representable value gU: kth value == gU
                s_status = 2;
                s_cntU = CU; s_sumU = SU; s_m = 0; s_thr = U;
            } else {
                bool done = false;
                if (CU < k && CL >= k) {            // bracketed
                    int mm = CL - CU;
                    if (mm <= BUFCAP) {
                        s_status = 1; s_cntU = CU; s_sumU = SU; s_m = mm;
                        done = true;
                    } else { gL = L; gU = U; }       // valid bracket but overflow -> bisect
                } else if (CU >= k) {
                    gL = U;                          // kth value above U
                } else {
                    gU = L;                          // kth value <= L
                }
                if (!done) {
                    if (__float_as_uint(gU) - __float_as_uint(gL) <= 1u) {
                        // 1-ulp window: all remaining candidates equal gU
                        tiemode = true;
                        s_Lb = gU; s_Ub = gU;
                    } else {
                        float mid = 0.5f * (gL + gU);
                        if (!(mid > gL && mid < gU))
                            mid = __uint_as_float((__float_as_uint(gL) + __float_as_uint(gU)) >> 1);
                        s_Lb = gL; s_Ub = mid;       // test lower half next
                    }
                }
            }
        }
        __syncthreads();
        if (s_status != 0) break;
    }

    __syncthreads();
    const int st = s_status;
    const int m  = s_m;

    if (st == 1) {
        // exact radix select: (k - cntU)-th largest among m floats in s_buf (all > 0)
        if (tid == 0) { s_prefix = 0u; s_kk = k - s_cntU; }
        for (int pos = 24; pos >= 0; pos -= 8) {
            __syncthreads();
            for (int j = tid; j < 256; j += TPB) s_hist[j] = 0;
            __syncthreads();
            const unsigned pref  = s_prefix;
            const unsigned pmask = (pos == 24) ? 0u : (0xffffffffu << (pos + 8));
            for (int i = tid; i < m; i += TPB) {
                unsigned v = __float_as_uint(s_buf[i]);
                if ((v & pmask) == pref)
                    atomicAdd(&s_hist[(v >> pos) & 255], 1);
            }
            __syncthreads();
            if (tid == 0) {
                int kk = s_kk;
                int c = 0, d = 255;
                for (; d >= 0; --d) { c += s_hist[d]; if (c >= kk) break; }
                if (d < 0) d = 0;                    // unreachable by invariant; safety
                s_kk = kk - (c - s_hist[d]);
                s_prefix = pref | ((unsigned)d << (unsigned)pos);
            }
        }
        __syncthreads();
        if (tid == 0) s_thr = __uint_as_float(s_prefix);
        __syncthreads();
    }

    // final: sum of window elements strictly above thr (+ tie correction)
    const float thr = s_thr;
    float sg = 0.0f; int cg = 0;
    for (int i = tid; i < m; i += TPB) {
        float x = s_buf[i];
        if (x > thr) { sg += x; cg++; }
    }
    sg = warpRedF(sg);
    cg = warpRedI(cg);
    if (lane == 0) { s_rf[wid] = sg; s_ri[wid] = cg; }
    __syncthreads();
    if (tid == 0) {
        float SG = 0.0f; int CG = 0;
        for (int j = 0; j < NWARP; ++j) { SG += s_rf[j]; CG += s_ri[j]; }
        float topk = s_sumU + SG + (float)(k - s_cntU - CG) * thr;
        float vl   = topk / (float)k;
        float lab  = label[row];
        float loss = -(lab * logf(vl) + (1.0f - lab) * log1pf(-vl));
        g_rowloss[row] = loss;
    }
}

__global__ void finalize_kernel(float* __restrict__ out, int B) {
    __shared__ float s[8];
    float v = 0.0f;
    for (int i = threadIdx.x; i < B; i += 256) v += g_rowloss[i];
    v = warpRedF(v);
    if ((threadIdx.x & 31) == 0) s[threadIdx.x >> 5] = v;
    __syncthreads();
    if (threadIdx.x == 0) {
        float t = 0.0f;
        for (int j = 0; j < 8; ++j) t += s[j];
        out[0] = t / (float)B;
    }
}

extern "C" void kernel_launch(void* const* d_in, const int* in_sizes, int n_in,
                              void* d_out, int out_size) {
    const float* scores = (const float*)d_in[0];
    const float* label  = (const float*)d_in[1];
    const int*   seqlen = (const int*)d_in[2];
    int B = in_sizes[1];
    if (B > MAXB) B = MAXB;
    int T = in_sizes[0] / B;

    topk_bce_kernel<<<B, TPB>>>(scores, label, seqlen, T);
    finalize_kernel<<<1, 256>>>((float*)d_out, B);
}

// round 2
// speedup vs baseline: 1.6693x; 1.6693x over previous
#include <cuda_runtime.h>
#include <math.h>

#define TPB 256
#define NWARP (TPB / 32)
#define BUFCAP 4096
#define MAXB 4096

__device__ float g_rowloss[MAXB];
__device__ unsigned g_done;   // zero-init at load; last block resets to 0 each launch

__device__ __forceinline__ float warpRedF(float v) {
#pragma unroll
    for (int o = 16; o > 0; o >>= 1) v += __shfl_down_sync(0xffffffffu, v, o);
    return v;
}
__device__ __forceinline__ int warpRedI(int v) {
#pragma unroll
    for (int o = 16; o > 0; o >>= 1) v += __shfl_down_sync(0xffffffffu, v, o);
    return v;
}

__global__ __launch_bounds__(TPB, 7) void topk_bce_kernel(
    const float* __restrict__ scores,
    const float* __restrict__ label,
    const int* __restrict__ seqlen,
    int T, int B,
    float* __restrict__ out)
{
    __shared__ float s_buf[BUFCAP];
    __shared__ int   s_hist[256];
    __shared__ float s_rf[NWARP];
    __shared__ int   s_ri[NWARP];
    __shared__ int   s_ri2[NWARP];
    __shared__ int   s_widx;
    __shared__ float s_Lb, s_Ub;
    __shared__ int   s_status;   // 0 continue, 1 select in buffer, 2 tie (thr known exactly)
    __shared__ int   s_m;
    __shared__ int   s_cntU;
    __shared__ float s_sumU;
    __shared__ unsigned s_prefix;
    __shared__ int   s_kk;
    __shared__ float s_thr;
    __shared__ int   s_last;

    const int row  = blockIdx.x;
    const int tid  = threadIdx.x;
    const int lane = tid & 31;
    const int wid  = tid >> 5;

    const int n = seqlen[row];
    const int k = (n >> 4) + 1;                 // seqlen//16 + 1, 1 <= k <= n
    const float*  rp  = scores + (size_t)row * (size_t)T;
    const float4* rp4 = (const float4*)rp;

    if (n <= BUFCAP) {
        // ---- small row: everything fits in SMEM, no streaming selection pass ----
        for (int i = tid; i < n; i += TPB) s_buf[i] = rp[i];
        if (tid == 0) {
            s_status = 1; s_m = n; s_cntU = 0; s_sumU = 0.0f; s_thr = 0.5f;
        }
        __syncthreads();
    } else {
        // ---- large row: statistical window pass (+ deterministic bisection fallback) ----
        float gL = 0.0f, gU = 1.0f;             // thread-0 bracket: kth value in (gL, gU]
        bool  tiemode = false;

        if (tid == 0) {
            float fn = (float)n, fk = (float)k;
            float mean = 1.0f - fk / fn;        // quantile of kth order statistic
            float sig  = sqrtf(fk) / fn;        // >= Beta std -> conservative
            s_Lb = fmaxf(0.0f, mean - 10.0f * sig);
            s_Ub = fminf(1.0f, mean + 10.0f * sig);
            s_status = 0; s_m = 0; s_thr = 0.5f; s_cntU = 0; s_sumU = 0.0f;
        }

        const int nv   = n >> 2;                // # of full float4s
        const int STEP = TPB * 2;
        const int nvr  = ((nv + STEP - 1) / STEP) * STEP;

        for (int iter = 0; iter < 64; ++iter) {
            __syncthreads();
            const float L = s_Lb, U = s_Ub;
            if (tid == 0) s_widx = 0;
            __syncthreads();

            int   cU = 0, cL = 0;
            float sU = 0.0f;

            for (int base = tid; base < nvr; base += STEP) {
                const int i1 = base + TPB;
                float4 a = (base < nv) ? rp4[base] : make_float4(-1.f, -1.f, -1.f, -1.f);
                float4 b = (i1   < nv) ? rp4[i1]   : make_float4(-1.f, -1.f, -1.f, -1.f);
                float xs[8] = {a.x, a.y, a.z, a.w, b.x, b.y, b.z, b.w};
#pragma unroll
                for (int c = 0; c < 8; ++c) {
                    float x = xs[c];
                    bool gtU = x > U;
                    bool gtL = x > L;
                    cL += gtL;
                    if (gtU) { cU++; sU += x; }
                    else if (gtL) {
                        int p = atomicAdd(&s_widx, 1);
                        if (p < BUFCAP) s_buf[p] = x;
                    }
                }
            }
            {   // scalar tail (< 4 elements)
                int i = (nv << 2) + tid;
                if (i < n) {
                    float x = rp[i];
                    bool gtU = x > U;
                    bool gtL = x > L;
                    cL += gtL;
                    if (gtU) { cU++; sU += x; }
                    else if (gtL) {
                        int p = atomicAdd(&s_widx, 1);
                        if (p < BUFCAP) s_buf[p] = x;
                    }
                }
            }

            cU = warpRedI(cU);
            cL = warpRedI(cL);
            sU = warpRedF(sU);
            if (lane == 0) { s_ri[wid] = cU; s_ri2[wid] = cL; s_rf[wid] = sU; }
            __syncthreads();

            if (tid == 0) {
                int CU = 0, CL = 0; float SU = 0.0f;
                for (int j = 0; j < NWARP; ++j) { CU += s_ri[j]; CL += s_ri2[j]; SU += s_rf[j]; }

                if (tiemode) {
                    // 1-ulp window collapsed: kth value == U exactly
                    s_status = 2; s_cntU = CU; s_sumU = SU; s_m = 0; s_thr = U;
                } else {
                    bool done = false;
                    if (CU < k && CL >= k) {
                        int mm = CL - CU;
                        if (mm <= BUFCAP) {
                            s_status = 1; s_cntU = CU; s_sumU = SU; s_m = mm;
                            done = true;
                        } else { gL = L; gU = U; }     // valid bracket, buffer overflow -> bisect
                    } else if (CU >= k) {
                        gL = U;
                    } else {
                        gU = L;
                    }
                    if (!done) {
                        if (__float_as_uint(gU) - __float_as_uint(gL) <= 1u) {
                            tiemode = true;
                            s_Lb = gU; s_Ub = gU;
                        } else {
                            float mid = 0.5f * (gL + gU);
                            if (!(mid > gL && mid < gU))
                                mid = __uint_as_float((__float_as_uint(gL) + __float_as_uint(gU)) >> 1);
                            s_Lb = gL; s_Ub = mid;
                        }
                    }
                }
            }
            __syncthreads();
            if (s_status != 0) break;
        }
        __syncthreads();
    }

    const int st = s_status;
    const int m  = s_m;

    if (st == 1) {
        // exact 8-bit radix select: (k - cntU)-th largest among m positive floats in s_buf
        if (tid == 0) { s_prefix = 0u; s_kk = k - s_cntU; }
        for (int pos = 24; pos >= 0; pos -= 8) {
            __syncthreads();
            for (int j = tid; j < 256; j += TPB) s_hist[j] = 0;
            __syncthreads();
            const unsigned pref  = s_prefix;
            const unsigned pmask = (pos == 24) ? 0u : (0xffffffffu << (pos + 8));
            for (int i = tid; i < m; i += TPB) {
                unsigned v = __float_as_uint(s_buf[i]);
                if ((v & pmask) == pref)
                    atomicAdd(&s_hist[(v >> pos) & 255], 1);
            }
            __syncthreads();
            if (tid == 0) {
                int kk = s_kk;
                int c = 0, d = 255;
                for (; d >= 0; --d) { c += s_hist[d]; if (c >= kk) break; }
                if (d < 0) d = 0;                       // unreachable; safety
                s_kk = kk - (c - s_hist[d]);
                s_prefix = pref | ((unsigned)d << (unsigned)pos);
            }
        }
        __syncthreads();
        if (tid == 0) s_thr = __uint_as_float(s_prefix);
        __syncthreads();
    }

    // exact tie-corrected top-k sum: sum(>U) + sum_window(>thr) + (k - cnt>thr) * thr
    const float thr = s_thr;
    float sg = 0.0f; int cg = 0;
    for (int i = tid; i < m; i += TPB) {
        float x = s_buf[i];
        if (x > thr) { sg += x; cg++; }
    }
    sg = warpRedF(sg);
    cg = warpRedI(cg);
    if (lane == 0) { s_rf[wid] = sg; s_ri[wid] = cg; }
    __syncthreads();
    if (tid == 0) {
        float SG = 0.0f; int CG = 0;
        for (int j = 0; j < NWARP; ++j) { SG += s_rf[j]; CG += s_ri[j]; }
        float topk = s_sumU + SG + (float)(k - s_cntU - CG) * thr;
        float vl   = topk / (float)k;
        float lab  = label[row];
        g_rowloss[row] = -(lab * logf(vl) + (1.0f - lab) * log1pf(-vl));
    }

    // ---- last-block-done: deterministic final reduction, no second kernel ----
    __threadfence();
    if (tid == 0) {
        unsigned t = atomicAdd(&g_done, 1u);
        s_last = (t == (unsigned)(gridDim.x - 1));
    }
    __syncthreads();
    if (s_last) {
        float v = 0.0f;
        for (int i = tid; i < B; i += TPB) v += g_rowloss[i];
        v = warpRedF(v);
        if (lane == 0) s_rf[wid] = v;
        __syncthreads();
        if (tid == 0) {
            float t = 0.0f;
            for (int j = 0; j < NWARP; ++j) t += s_rf[j];
            out[0] = t / (float)B;
            g_done = 0;                      // reset for next graph replay
        }
    }
}

extern "C" void kernel_launch(void* const* d_in, const int* in_sizes, int n_in,
                              void* d_out, int out_size) {
    const float* scores = (const float*)d_in[0];
    const float* label  = (const float*)d_in[1];
    const int*   seqlen = (const int*)d_in[2];
    int B = in_sizes[1];
    if (B > MAXB) B = MAXB;
    int T = in_sizes[0] / B;

    topk_bce_kernel<<<B, TPB>>>(scores, label, seqlen, T, B, (float*)d_out);
}